// round 2
// baseline (speedup 1.0000x reference)
#include <cuda_runtime.h>
#include <stdint.h>

#define NBUCK 65536
#define CAP   2048
#define K_FG  128
#define K_BG  512
#define TOTAL 512
#define NCLS  21
#define NMAX  200000
#define MMAX  256

// ---------------- global scratch (no allocations allowed) ----------------
__device__ unsigned int      g_hist[2 * NBUCK];
__device__ unsigned int      g_rbits[NMAX];
__device__ int               g_argmax[NMAX];
__device__ unsigned char     g_flag[NMAX];
__device__ unsigned int      g_nfg;
__device__ int               g_cut[2];
__device__ unsigned int      g_candcnt[2];
__device__ unsigned long long g_cand[2 * CAP];
__device__ int               g_top[K_FG + K_BG];   // fg[128] then bg[512]

// ---------------- Threefry-2x32, key = (0, 42) (jax.random.key(42)) -------
__device__ __forceinline__ uint32_t rotl32(uint32_t x, int d) {
    return (x << d) | (x >> (32 - d));
}

__device__ __forceinline__ void threefry_0_42(uint32_t x0, uint32_t x1,
                                              uint32_t& o0, uint32_t& o1) {
    const uint32_t ks0 = 0u, ks1 = 42u, ks2 = 0x1BD11BDAu ^ 0u ^ 42u;
    x0 += ks0; x1 += ks1;
#define TF_R(r) { x0 += x1; x1 = rotl32(x1, r); x1 ^= x0; }
    TF_R(13) TF_R(15) TF_R(26) TF_R(6)  x0 += ks1; x1 += ks2 + 1u;
    TF_R(17) TF_R(29) TF_R(16) TF_R(24) x0 += ks2; x1 += ks0 + 2u;
    TF_R(13) TF_R(15) TF_R(26) TF_R(6)  x0 += ks0; x1 += ks1 + 3u;
    TF_R(17) TF_R(29) TF_R(16) TF_R(24) x0 += ks1; x1 += ks2 + 4u;
    TF_R(13) TF_R(15) TF_R(26) TF_R(6)  x0 += ks2; x1 += ks0 + 5u;
#undef TF_R
    o0 = x0; o1 = x1;
}

// ---------------- K0: zero the per-launch mutable scratch -----------------
__global__ void k_init() {
    int i = blockIdx.x * blockDim.x + threadIdx.x;
    if (i < 2 * NBUCK) g_hist[i] = 0u;
    if (i == 0) { g_nfg = 0u; g_candcnt[0] = 0u; g_candcnt[1] = 0u; }
}

// ---------------- K1: PRNG + IoU max/argmax + classify + histogram --------
__global__ void __launch_bounds__(256) k_main(const float* __restrict__ rois,
                                              const float* __restrict__ gtb,
                                              int n, int m) {
    __shared__ float4 sg[MMAX];
    __shared__ float  sa[MMAX];
    __shared__ unsigned int s_nfg;
    if (threadIdx.x == 0) s_nfg = 0u;
    for (int j = threadIdx.x; j < m; j += blockDim.x) {
        float x1 = gtb[4 * j + 0], y1 = gtb[4 * j + 1];
        float x2 = gtb[4 * j + 2], y2 = gtb[4 * j + 3];
        sg[j] = make_float4(x1, y1, x2, y2);
        sa[j] = __fmul_rn(__fadd_rn(__fsub_rn(x2, x1), 1.0f),
                          __fadd_rn(__fsub_rn(y2, y1), 1.0f));
    }
    __syncthreads();

    int i = blockIdx.x * blockDim.x + threadIdx.x;
    if (i < n) {
        // --- exact JAX uniform (threefry_partitionable=True, default since
        //     JAX 0.4.30): per-element uint64 iota counter -> (hi32=0, lo32=i),
        //     32-bit draw combines the pair as o0 ^ o1.
        uint32_t o0, o1;
        threefry_0_42(0u, (uint32_t)i, o0, o1);
        uint32_t raw = o0 ^ o1;
        float r = __uint_as_float((raw >> 9) | 0x3F800000u) - 1.0f;
        g_rbits[i] = __float_as_uint(r);

        // --- IoU argmax over m gts (exact real ordering via fp64 cross-mul)
        float ax1 = rois[4 * i + 0], ay1 = rois[4 * i + 1];
        float ax2 = rois[4 * i + 2], ay2 = rois[4 * i + 3];
        float areaA = __fmul_rn(__fadd_rn(__fsub_rn(ax2, ax1), 1.0f),
                                __fadd_rn(__fsub_rn(ay2, ay1), 1.0f));
        float bestI = 0.0f, bestU = 1.0f;
        int arg = 0;
#pragma unroll 4
        for (int j = 0; j < m; j++) {
            float4 g = sg[j];
            float w = __fadd_rn(__fsub_rn(fminf(ax2, g.z), fmaxf(ax1, g.x)), 1.0f);
            float h = __fadd_rn(__fsub_rn(fminf(ay2, g.w), fmaxf(ay1, g.y)), 1.0f);
            w = fmaxf(w, 0.0f); h = fmaxf(h, 0.0f);
            float inter = __fmul_rn(w, h);
            float u = __fsub_rn(__fadd_rn(areaA, sa[j]), inter);
            if (inter > 0.0f && u > 0.0f) {
                if ((double)inter * (double)bestU > (double)bestI * (double)u) {
                    bestI = inter; bestU = u; arg = j;
                }
            }
        }
        g_argmax[i] = arg;
        float mx = __fdiv_rn(bestI, bestU);   // IEEE, matches reference value

        int flag = 0;
        if (mx > 0.5f) flag = 1;
        else if (mx < 0.5f) flag = 2;
        g_flag[i] = (unsigned char)flag;
        if (flag) {
            uint32_t b = (uint32_t)(r * 65536.0f);   // exact *2^16 -> monotone
            atomicAdd(&g_hist[(flag - 1) * NBUCK + b], 1u);
            if (flag == 1) atomicAdd(&s_nfg, 1u);
        }
    }
    __syncthreads();
    if (threadIdx.x == 0 && s_nfg) atomicAdd(&g_nfg, s_nfg);
}

// ---------------- K2: suffix-scan the histograms to find cutoff buckets ---
__global__ void k_cutoff() {
    __shared__ unsigned int csum[1024];
    for (int c = 0; c < 2; c++) {
        unsigned int k = (c == 0) ? K_FG : K_BG;
        unsigned int s = 0;
        int base = c * NBUCK + threadIdx.x * 64;
#pragma unroll 8
        for (int q = 0; q < 64; q++) s += g_hist[base + q];
        csum[threadIdx.x] = s;
        __syncthreads();
        if (threadIdx.x == 0) {
            unsigned int cum = 0;
            int chunk = 1023;
            for (; chunk >= 0; chunk--) { cum += csum[chunk]; if (cum >= k) break; }
            int cut = 0;
            if (chunk >= 0) {
                unsigned int cum2 = cum - csum[chunk];
                cut = chunk * 64;
                for (int b = chunk * 64 + 63; b >= chunk * 64; b--) {
                    cum2 += g_hist[c * NBUCK + b];
                    if (cum2 >= k) { cut = b; break; }
                }
            }
            g_cut[c] = cut;
        }
        __syncthreads();
    }
}

// ---------------- K3: compact candidates above the cutoff -----------------
__global__ void k_compact(int n) {
    int i = blockIdx.x * blockDim.x + threadIdx.x;
    if (i >= n) return;
    int f = g_flag[i];
    if (!f) return;
    int c = f - 1;
    uint32_t rb = g_rbits[i];
    float r = __uint_as_float(rb);
    int b = (int)(r * 65536.0f);
    if (b >= g_cut[c]) {
        unsigned int p = atomicAdd(&g_candcnt[c], 1u);
        if (p < CAP) {
            // ascending sort key: smaller == larger r; tie -> lower index first
            g_cand[c * CAP + p] =
                ((unsigned long long)(~rb) << 32) | (unsigned int)i;
        }
    }
}

// ---------------- K4: bitonic sort (block 0 = fg, block 1 = bg) -----------
__global__ void __launch_bounds__(1024) k_sort() {
    __shared__ unsigned long long s[CAP];
    int c = blockIdx.x;
    unsigned int cnt = g_candcnt[c];
    if (cnt > CAP) cnt = CAP;
    for (int t = threadIdx.x; t < CAP; t += 1024)
        s[t] = (t < (int)cnt) ? g_cand[c * CAP + t] : ~0ULL;
    __syncthreads();
    for (int k = 2; k <= CAP; k <<= 1) {
        for (int j = k >> 1; j > 0; j >>= 1) {
            for (int t = threadIdx.x; t < CAP; t += 1024) {
                int ixj = t ^ j;
                if (ixj > t) {
                    bool up = ((t & k) == 0);
                    unsigned long long a = s[t], b = s[ixj];
                    if ((a > b) == up) { s[t] = b; s[ixj] = a; }
                }
            }
            __syncthreads();
        }
    }
    int k_out = (c == 0) ? K_FG : K_BG;
    int off   = (c == 0) ? 0    : K_FG;
    for (int t = threadIdx.x; t < k_out; t += 1024)
        g_top[off + t] = (int)(unsigned int)(s[t] & 0xFFFFFFFFu);
}

// ---------------- K5: build all five outputs (float32, tuple order) -------
__global__ void __launch_bounds__(TOTAL) k_output(const float* __restrict__ rois,
                                                  const float* __restrict__ gtb,
                                                  const int* __restrict__ glab,
                                                  float* __restrict__ out, int n) {
    int s = threadIdx.x;
    if (s >= TOTAL) return;
    int nfg = min((int)g_nfg, K_FG);
    bool isfg = s < nfg;
    int keep;
    if (isfg) keep = g_top[s];
    else {
        int bs = s - nfg;
        bs = bs < 0 ? 0 : (bs > K_BG - 1 ? K_BG - 1 : bs);
        keep = g_top[K_FG + bs];
    }
    if (keep < 0 || keep >= n) keep = 0;   // safety (unreachable for this input)

    float rx1 = rois[4 * keep + 0], ry1 = rois[4 * keep + 1];
    float rx2 = rois[4 * keep + 2], ry2 = rois[4 * keep + 3];
    out[4 * s + 0] = rx1; out[4 * s + 1] = ry1;
    out[4 * s + 2] = rx2; out[4 * s + 3] = ry2;

    int ga  = g_argmax[keep];
    int lab = glab[ga];
    out[TOTAL * 4 + s] = isfg ? (float)lab : 0.0f;

    float e0 = 0.f, e1 = 0.f, e2 = 0.f, e3 = 0.f;
    if (isfg) {
        float gx1 = gtb[4 * ga + 0], gy1 = gtb[4 * ga + 1];
        float gx2 = gtb[4 * ga + 2], gy2 = gtb[4 * ga + 3];
        float rw = fmaxf(rx2 - rx1 + 1.0f, 1e-6f);
        float rh = fmaxf(ry2 - ry1 + 1.0f, 1e-6f);
        float rcx = rx1 + 0.5f * rw, rcy = ry1 + 0.5f * rh;
        float gw = fmaxf(gx2 - gx1 + 1.0f, 1e-6f);
        float gh = fmaxf(gy2 - gy1 + 1.0f, 1e-6f);
        float gcx = gx1 + 0.5f * gw, gcy = gy1 + 0.5f * gh;
        e0 = (gcx - rcx) / rw;
        e1 = (gcy - rcy) / rh;
        e2 = logf(gw / rw);
        e3 = logf(gh / rh);
    }

    const int TGT = TOTAL * 4 + TOTAL;           // 2560
    const int INW = TGT + TOTAL * NCLS * 4;      // 45568
    const int OUW = INW + TOTAL * NCLS * 4;      // 88576
    int L = isfg ? lab : -1;
#pragma unroll
    for (int c = 0; c < NCLS; c++) {
        bool hit = (c == L);
        int o = s * (NCLS * 4) + 4 * c;
        out[TGT + o + 0] = hit ? e0 : 0.f;
        out[TGT + o + 1] = hit ? e1 : 0.f;
        out[TGT + o + 2] = hit ? e2 : 0.f;
        out[TGT + o + 3] = hit ? e3 : 0.f;
        float w = hit ? 1.f : 0.f;
        out[INW + o + 0] = w; out[INW + o + 1] = w;
        out[INW + o + 2] = w; out[INW + o + 3] = w;
        out[OUW + o + 0] = 1.f; out[OUW + o + 1] = 1.f;
        out[OUW + o + 2] = 1.f; out[OUW + o + 3] = 1.f;
    }
}

// ---------------- launcher -------------------------------------------------
extern "C" void kernel_launch(void* const* d_in, const int* in_sizes, int n_in,
                              void* d_out, int out_size) {
    // Identify inputs by size (rois: 4N, gt_bboxes: 4M, gt_labels: M)
    int i_rois = 0;
    for (int i = 0; i < n_in; i++)
        if (in_sizes[i] > in_sizes[i_rois]) i_rois = i;
    int i_gtb = -1, i_lab = -1;
    {
        int a = -1, b = -1;
        for (int i = 0; i < n_in; i++) if (i != i_rois) { if (a < 0) a = i; else b = i; }
        if (in_sizes[a] < in_sizes[b]) { i_lab = a; i_gtb = b; }
        else                           { i_lab = b; i_gtb = a; }
    }

    const float* rois = (const float*)d_in[i_rois];
    const float* gtb  = (const float*)d_in[i_gtb];
    const int*   glab = (const int*)d_in[i_lab];
    float* out = (float*)d_out;

    int n = in_sizes[i_rois] / 4;
    if (n > NMAX) n = NMAX;
    int m = in_sizes[i_gtb] / 4;
    if (m > MMAX) m = MMAX;

    k_init<<<(2 * NBUCK + 255) / 256, 256>>>();
    k_main<<<(n + 255) / 256, 256>>>(rois, gtb, n, m);
    k_cutoff<<<1, 1024>>>();
    k_compact<<<(n + 255) / 256, 256>>>(n);
    k_sort<<<2, 1024>>>();
    k_output<<<1, TOTAL>>>(rois, gtb, glab, out, n);
}

// round 3
// speedup vs baseline: 2.5084x; 2.5084x over previous
#include <cuda_runtime.h>
#include <stdint.h>

#define NBUCK 65536
#define CAP   2048
#define K_FG  128
#define K_BG  512
#define TOTAL 512
#define NCLS  21
#define NMAX  200000
#define MMAX  256

#define GC       20          // 20x20 cells, 64px each, origin -128 -> covers [-128,1152)
#define GORG     128.0f
#define GINV     (1.0f/64.0f)
#define GIDX_CAP 4608        // >= 256 gts * 16 cells worst case

// ---------------- global scratch (no allocations allowed) ----------------
__device__ unsigned int      g_hist[2 * NBUCK];
__device__ unsigned int      g_rbits[NMAX];
__device__ int               g_argmax[NMAX];
__device__ unsigned char     g_flag[NMAX];
__device__ unsigned int      g_nfg;
__device__ int               g_cut[2];
__device__ unsigned int      g_candcnt[2];
__device__ unsigned long long g_cand[2 * CAP];
__device__ int               g_top[K_FG + K_BG];   // fg[128] then bg[512]
__device__ int               g_goff[GC * GC + 1];  // CSR offsets for gt grid
__device__ unsigned char     g_gidx[GIDX_CAP];     // CSR gt indices

// ---------------- Threefry-2x32, key = (0, 42) (jax.random.key(42)) -------
__device__ __forceinline__ uint32_t rotl32(uint32_t x, int d) {
    return (x << d) | (x >> (32 - d));
}

__device__ __forceinline__ void threefry_0_42(uint32_t x0, uint32_t x1,
                                              uint32_t& o0, uint32_t& o1) {
    const uint32_t ks0 = 0u, ks1 = 42u, ks2 = 0x1BD11BDAu ^ 0u ^ 42u;
    x0 += ks0; x1 += ks1;
#define TF_R(r) { x0 += x1; x1 = rotl32(x1, r); x1 ^= x0; }
    TF_R(13) TF_R(15) TF_R(26) TF_R(6)  x0 += ks1; x1 += ks2 + 1u;
    TF_R(17) TF_R(29) TF_R(16) TF_R(24) x0 += ks2; x1 += ks0 + 2u;
    TF_R(13) TF_R(15) TF_R(26) TF_R(6)  x0 += ks0; x1 += ks1 + 3u;
    TF_R(17) TF_R(29) TF_R(16) TF_R(24) x0 += ks1; x1 += ks2 + 4u;
    TF_R(13) TF_R(15) TF_R(26) TF_R(6)  x0 += ks2; x1 += ks0 + 5u;
#undef TF_R
    o0 = x0; o1 = x1;
}

__device__ __forceinline__ int cell_of(float x) {
    int c = (int)floorf((x + GORG) * GINV);
    return min(max(c, 0), GC - 1);
}

// ---------------- K0: zero the per-launch mutable scratch -----------------
__global__ void k_init() {
    int i = blockIdx.x * blockDim.x + threadIdx.x;
    if (i < 2 * NBUCK) g_hist[i] = 0u;
    if (i == 0) { g_nfg = 0u; g_candcnt[0] = 0u; g_candcnt[1] = 0u; }
}

// ---------------- K0b: build gt spatial grid (CSR), one block -------------
__global__ void __launch_bounds__(256) k_grid(const float* __restrict__ gtb, int m) {
    __shared__ int cnt[GC * GC];
    __shared__ int cur[GC * GC];
    int tid = threadIdx.x;
    for (int c = tid; c < GC * GC; c += blockDim.x) cnt[c] = 0;
    __syncthreads();
    for (int j = tid; j < m; j += blockDim.x) {
        int cx0 = cell_of(gtb[4 * j + 0]), cy0 = cell_of(gtb[4 * j + 1]);
        int cx1 = cell_of(gtb[4 * j + 2]), cy1 = cell_of(gtb[4 * j + 3]);
        for (int cy = cy0; cy <= cy1; cy++)
            for (int cx = cx0; cx <= cx1; cx++)
                atomicAdd(&cnt[cy * GC + cx], 1);
    }
    __syncthreads();
    if (tid == 0) {
        int acc = 0;
        for (int c = 0; c < GC * GC; c++) {
            cur[c] = acc; g_goff[c] = acc; acc += cnt[c];
        }
        g_goff[GC * GC] = acc;
    }
    __syncthreads();
    for (int j = tid; j < m; j += blockDim.x) {
        int cx0 = cell_of(gtb[4 * j + 0]), cy0 = cell_of(gtb[4 * j + 1]);
        int cx1 = cell_of(gtb[4 * j + 2]), cy1 = cell_of(gtb[4 * j + 3]);
        for (int cy = cy0; cy <= cy1; cy++)
            for (int cx = cx0; cx <= cx1; cx++) {
                int p = atomicAdd(&cur[cy * GC + cx], 1);
                g_gidx[p] = (unsigned char)j;
            }
    }
}

// ---------------- K1: PRNG + pruned IoU max/argmax + classify + hist ------
__global__ void __launch_bounds__(256) k_main(const float* __restrict__ rois,
                                              const float* __restrict__ gtb,
                                              int n, int m) {
    __shared__ float4 sg[MMAX];
    __shared__ float  sa[MMAX];
    __shared__ int    soff[GC * GC + 1];
    __shared__ unsigned char sidx[GIDX_CAP];
    __shared__ unsigned int s_nfg;
    int tid = threadIdx.x;
    if (tid == 0) s_nfg = 0u;
    for (int j = tid; j < m; j += blockDim.x) {
        float x1 = gtb[4 * j + 0], y1 = gtb[4 * j + 1];
        float x2 = gtb[4 * j + 2], y2 = gtb[4 * j + 3];
        sg[j] = make_float4(x1, y1, x2, y2);
        sa[j] = __fmul_rn(__fadd_rn(__fsub_rn(x2, x1), 1.0f),
                          __fadd_rn(__fsub_rn(y2, y1), 1.0f));
    }
    int total = g_goff[GC * GC];
    for (int c = tid; c < GC * GC + 1; c += blockDim.x) soff[c] = g_goff[c];
    for (int t = tid; t < total; t += blockDim.x) sidx[t] = g_gidx[t];
    __syncthreads();

    int i = blockIdx.x * blockDim.x + tid;
    if (i < n) {
        // --- exact JAX uniform (threefry_partitionable=True default):
        //     per-element u64 iota counter (0, i); 32-bit draw = o0 ^ o1
        uint32_t o0, o1;
        threefry_0_42(0u, (uint32_t)i, o0, o1);
        uint32_t raw = o0 ^ o1;
        float r = __uint_as_float((raw >> 9) | 0x3F800000u) - 1.0f;
        g_rbits[i] = __float_as_uint(r);

        // --- pruned IoU argmax (fp32-division ordering == reference)
        float4 a = reinterpret_cast<const float4*>(rois)[i];
        float areaA = __fmul_rn(__fadd_rn(__fsub_rn(a.z, a.x), 1.0f),
                                __fadd_rn(__fsub_rn(a.w, a.y), 1.0f));
        float bestIou = 0.0f;
        int arg = 0;
        int cx0 = cell_of(a.x - 2.0f), cx1 = cell_of(a.z + 2.0f);
        int cy0 = cell_of(a.y - 2.0f), cy1 = cell_of(a.w + 2.0f);
        for (int cy = cy0; cy <= cy1; cy++) {
            for (int cx = cx0; cx <= cx1; cx++) {
                int cell = cy * GC + cx;
                int b0 = soff[cell], b1 = soff[cell + 1];
                for (int t = b0; t < b1; t++) {
                    int j = sidx[t];
                    float4 g = sg[j];
                    float w = __fadd_rn(__fsub_rn(fminf(a.z, g.z),
                                                  fmaxf(a.x, g.x)), 1.0f);
                    float h = __fadd_rn(__fsub_rn(fminf(a.w, g.w),
                                                  fmaxf(a.y, g.y)), 1.0f);
                    if (w > 0.0f && h > 0.0f) {
                        float inter = __fmul_rn(w, h);
                        float u = __fsub_rn(__fadd_rn(areaA, sa[j]), inter);
                        float iou = __fdiv_rn(inter, u);
                        if (iou > bestIou || (iou == bestIou && j < arg)) {
                            bestIou = iou; arg = j;
                        }
                    }
                }
            }
        }
        g_argmax[i] = arg;

        int flag = 0;
        if (bestIou > 0.5f) flag = 1;
        else if (bestIou < 0.5f) flag = 2;
        g_flag[i] = (unsigned char)flag;
        if (flag) {
            uint32_t b = (uint32_t)(r * 65536.0f);   // exact *2^16 -> monotone
            atomicAdd(&g_hist[(flag - 1) * NBUCK + b], 1u);
            if (flag == 1) atomicAdd(&s_nfg, 1u);
        }
    }
    __syncthreads();
    if (tid == 0 && s_nfg) atomicAdd(&g_nfg, s_nfg);
}

// ---------------- K2: suffix-scan the histograms to find cutoff buckets ---
__global__ void k_cutoff() {
    __shared__ unsigned int csum[1024];
    for (int c = 0; c < 2; c++) {
        unsigned int k = (c == 0) ? K_FG : K_BG;
        unsigned int s = 0;
        int base = c * NBUCK + threadIdx.x * 64;
#pragma unroll 8
        for (int q = 0; q < 64; q++) s += g_hist[base + q];
        csum[threadIdx.x] = s;
        __syncthreads();
        if (threadIdx.x == 0) {
            unsigned int cum = 0;
            int chunk = 1023;
            for (; chunk >= 0; chunk--) { cum += csum[chunk]; if (cum >= k) break; }
            int cut = 0;
            if (chunk >= 0) {
                unsigned int cum2 = cum - csum[chunk];
                cut = chunk * 64;
                for (int b = chunk * 64 + 63; b >= chunk * 64; b--) {
                    cum2 += g_hist[c * NBUCK + b];
                    if (cum2 >= k) { cut = b; break; }
                }
            }
            g_cut[c] = cut;
        }
        __syncthreads();
    }
}

// ---------------- K3: compact candidates above the cutoff -----------------
__global__ void k_compact(int n) {
    int i = blockIdx.x * blockDim.x + threadIdx.x;
    if (i >= n) return;
    int f = g_flag[i];
    if (!f) return;
    int c = f - 1;
    uint32_t rb = g_rbits[i];
    float r = __uint_as_float(rb);
    int b = (int)(r * 65536.0f);
    if (b >= g_cut[c]) {
        unsigned int p = atomicAdd(&g_candcnt[c], 1u);
        if (p < CAP) {
            // ascending sort key: smaller == larger r; tie -> lower index first
            g_cand[c * CAP + p] =
                ((unsigned long long)(~rb) << 32) | (unsigned int)i;
        }
    }
}

// ---------------- K4: bitonic sort (block 0 = fg, block 1 = bg) -----------
__global__ void __launch_bounds__(1024) k_sort() {
    __shared__ unsigned long long s[CAP];
    int c = blockIdx.x;
    unsigned int cnt = g_candcnt[c];
    if (cnt > CAP) cnt = CAP;
    for (int t = threadIdx.x; t < CAP; t += 1024)
        s[t] = (t < (int)cnt) ? g_cand[c * CAP + t] : ~0ULL;
    __syncthreads();
    for (int k = 2; k <= CAP; k <<= 1) {
        for (int j = k >> 1; j > 0; j >>= 1) {
            for (int t = threadIdx.x; t < CAP; t += 1024) {
                int ixj = t ^ j;
                if (ixj > t) {
                    bool up = ((t & k) == 0);
                    unsigned long long a = s[t], b = s[ixj];
                    if ((a > b) == up) { s[t] = b; s[ixj] = a; }
                }
            }
            __syncthreads();
        }
    }
    int k_out = (c == 0) ? K_FG : K_BG;
    int off   = (c == 0) ? 0    : K_FG;
    for (int t = threadIdx.x; t < k_out; t += 1024)
        g_top[off + t] = (int)(unsigned int)(s[t] & 0xFFFFFFFFu);
}

// ---------------- K5: build all five outputs (float32, tuple order) -------
__global__ void __launch_bounds__(TOTAL) k_output(const float* __restrict__ rois,
                                                  const float* __restrict__ gtb,
                                                  const int* __restrict__ glab,
                                                  float* __restrict__ out, int n) {
    int s = threadIdx.x;
    if (s >= TOTAL) return;
    int nfg = min((int)g_nfg, K_FG);
    bool isfg = s < nfg;
    int keep;
    if (isfg) keep = g_top[s];
    else {
        int bs = s - nfg;
        bs = bs < 0 ? 0 : (bs > K_BG - 1 ? K_BG - 1 : bs);
        keep = g_top[K_FG + bs];
    }
    if (keep < 0 || keep >= n) keep = 0;   // safety (unreachable for this input)

    float rx1 = rois[4 * keep + 0], ry1 = rois[4 * keep + 1];
    float rx2 = rois[4 * keep + 2], ry2 = rois[4 * keep + 3];
    out[4 * s + 0] = rx1; out[4 * s + 1] = ry1;
    out[4 * s + 2] = rx2; out[4 * s + 3] = ry2;

    int ga  = g_argmax[keep];
    int lab = glab[ga];
    out[TOTAL * 4 + s] = isfg ? (float)lab : 0.0f;

    float e0 = 0.f, e1 = 0.f, e2 = 0.f, e3 = 0.f;
    if (isfg) {
        float gx1 = gtb[4 * ga + 0], gy1 = gtb[4 * ga + 1];
        float gx2 = gtb[4 * ga + 2], gy2 = gtb[4 * ga + 3];
        float rw = fmaxf(rx2 - rx1 + 1.0f, 1e-6f);
        float rh = fmaxf(ry2 - ry1 + 1.0f, 1e-6f);
        float rcx = rx1 + 0.5f * rw, rcy = ry1 + 0.5f * rh;
        float gw = fmaxf(gx2 - gx1 + 1.0f, 1e-6f);
        float gh = fmaxf(gy2 - gy1 + 1.0f, 1e-6f);
        float gcx = gx1 + 0.5f * gw, gcy = gy1 + 0.5f * gh;
        e0 = (gcx - rcx) / rw;
        e1 = (gcy - rcy) / rh;
        e2 = logf(gw / rw);
        e3 = logf(gh / rh);
    }

    const int TGT = TOTAL * 4 + TOTAL;           // 2560
    const int INW = TGT + TOTAL * NCLS * 4;      // 45568
    const int OUW = INW + TOTAL * NCLS * 4;      // 88576
    int L = isfg ? lab : -1;
#pragma unroll
    for (int c = 0; c < NCLS; c++) {
        bool hit = (c == L);
        int o = s * (NCLS * 4) + 4 * c;
        out[TGT + o + 0] = hit ? e0 : 0.f;
        out[TGT + o + 1] = hit ? e1 : 0.f;
        out[TGT + o + 2] = hit ? e2 : 0.f;
        out[TGT + o + 3] = hit ? e3 : 0.f;
        float w = hit ? 1.f : 0.f;
        out[INW + o + 0] = w; out[INW + o + 1] = w;
        out[INW + o + 2] = w; out[INW + o + 3] = w;
        out[OUW + o + 0] = 1.f; out[OUW + o + 1] = 1.f;
        out[OUW + o + 2] = 1.f; out[OUW + o + 3] = 1.f;
    }
}

// ---------------- launcher -------------------------------------------------
extern "C" void kernel_launch(void* const* d_in, const int* in_sizes, int n_in,
                              void* d_out, int out_size) {
    // Identify inputs by size (rois: 4N, gt_bboxes: 4M, gt_labels: M)
    int i_rois = 0;
    for (int i = 0; i < n_in; i++)
        if (in_sizes[i] > in_sizes[i_rois]) i_rois = i;
    int i_gtb = -1, i_lab = -1;
    {
        int a = -1, b = -1;
        for (int i = 0; i < n_in; i++) if (i != i_rois) { if (a < 0) a = i; else b = i; }
        if (in_sizes[a] < in_sizes[b]) { i_lab = a; i_gtb = b; }
        else                           { i_lab = b; i_gtb = a; }
    }

    const float* rois = (const float*)d_in[i_rois];
    const float* gtb  = (const float*)d_in[i_gtb];
    const int*   glab = (const int*)d_in[i_lab];
    float* out = (float*)d_out;

    int n = in_sizes[i_rois] / 4;
    if (n > NMAX) n = NMAX;
    int m = in_sizes[i_gtb] / 4;
    if (m > MMAX) m = MMAX;

    k_init<<<(2 * NBUCK + 255) / 256, 256>>>();
    k_grid<<<1, 256>>>(gtb, m);
    k_main<<<(n + 255) / 256, 256>>>(rois, gtb, n, m);
    k_cutoff<<<1, 1024>>>();
    k_compact<<<(n + 255) / 256, 256>>>(n);
    k_sort<<<2, 1024>>>();
    k_output<<<1, TOTAL>>>(rois, gtb, glab, out, n);
}

// round 4
// speedup vs baseline: 3.0394x; 1.2117x over previous
#include <cuda_runtime.h>
#include <stdint.h>

#define NBUCK 4096
#define CAP   2048
#define K_FG  128
#define K_BG  512
#define TOTAL 512
#define NCLS  21
#define NMAX  200000
#define MMAX  256
#define RPT   4              // rois per thread in k_main

#define GC       20          // 20x20 cells, 64px each, origin -128 -> covers [-128,1152)
#define GORG     128.0f
#define GINV     (1.0f/64.0f)
#define GIDX_CAP 4608

// ---------------- global scratch (no allocations allowed) ----------------
__device__ unsigned int      g_hist[2 * NBUCK];
__device__ unsigned int      g_rbits[NMAX];
__device__ int               g_argmax[NMAX];
__device__ unsigned char     g_flag[NMAX];
__device__ unsigned int      g_nfg;
__device__ int               g_cut[2];
__device__ unsigned int      g_candcnt[2];
__device__ unsigned long long g_cand[2 * CAP];
__device__ int               g_top[K_FG + K_BG];   // fg[128] then bg[512]
__device__ int               g_goff[GC * GC + 1];  // CSR offsets for gt grid
__device__ unsigned char     g_gidx[GIDX_CAP];     // CSR gt indices

// ---------------- Threefry-2x32, key = (0, 42) (jax.random.key(42)) -------
__device__ __forceinline__ uint32_t rotl32(uint32_t x, int d) {
    return (x << d) | (x >> (32 - d));
}

__device__ __forceinline__ void threefry_0_42(uint32_t x0, uint32_t x1,
                                              uint32_t& o0, uint32_t& o1) {
    const uint32_t ks0 = 0u, ks1 = 42u, ks2 = 0x1BD11BDAu ^ 0u ^ 42u;
    x0 += ks0; x1 += ks1;
#define TF_R(r) { x0 += x1; x1 = rotl32(x1, r); x1 ^= x0; }
    TF_R(13) TF_R(15) TF_R(26) TF_R(6)  x0 += ks1; x1 += ks2 + 1u;
    TF_R(17) TF_R(29) TF_R(16) TF_R(24) x0 += ks2; x1 += ks0 + 2u;
    TF_R(13) TF_R(15) TF_R(26) TF_R(6)  x0 += ks0; x1 += ks1 + 3u;
    TF_R(17) TF_R(29) TF_R(16) TF_R(24) x0 += ks1; x1 += ks2 + 4u;
    TF_R(13) TF_R(15) TF_R(26) TF_R(6)  x0 += ks2; x1 += ks0 + 5u;
#undef TF_R
    o0 = x0; o1 = x1;
}

__device__ __forceinline__ int cell_of(float x) {
    int c = (int)floorf((x + GORG) * GINV);
    return min(max(c, 0), GC - 1);
}

// ---------------- K0: zero scratch + build gt spatial grid (one block) ----
__global__ void __launch_bounds__(256) k_grid(const float* __restrict__ gtb, int m) {
    __shared__ int cnt[GC * GC];
    __shared__ int cur[GC * GC];
    int tid = threadIdx.x;
    for (int i = tid; i < 2 * NBUCK; i += blockDim.x) g_hist[i] = 0u;
    if (tid == 0) { g_nfg = 0u; g_candcnt[0] = 0u; g_candcnt[1] = 0u; }
    for (int c = tid; c < GC * GC; c += blockDim.x) cnt[c] = 0;
    __syncthreads();
    for (int j = tid; j < m; j += blockDim.x) {
        int cx0 = cell_of(gtb[4 * j + 0]), cy0 = cell_of(gtb[4 * j + 1]);
        int cx1 = cell_of(gtb[4 * j + 2]), cy1 = cell_of(gtb[4 * j + 3]);
        for (int cy = cy0; cy <= cy1; cy++)
            for (int cx = cx0; cx <= cx1; cx++)
                atomicAdd(&cnt[cy * GC + cx], 1);
    }
    __syncthreads();
    if (tid == 0) {
        int acc = 0;
        for (int c = 0; c < GC * GC; c++) {
            cur[c] = acc; g_goff[c] = acc; acc += cnt[c];
        }
        g_goff[GC * GC] = acc;
    }
    __syncthreads();
    for (int j = tid; j < m; j += blockDim.x) {
        int cx0 = cell_of(gtb[4 * j + 0]), cy0 = cell_of(gtb[4 * j + 1]);
        int cx1 = cell_of(gtb[4 * j + 2]), cy1 = cell_of(gtb[4 * j + 3]);
        for (int cy = cy0; cy <= cy1; cy++)
            for (int cx = cx0; cx <= cx1; cx++) {
                int p = atomicAdd(&cur[cy * GC + cx], 1);
                g_gidx[p] = (unsigned char)j;
            }
    }
}

// ---------------- K1: PRNG + pruned IoU max/argmax + classify + hist ------
__global__ void __launch_bounds__(256) k_main(const float* __restrict__ rois,
                                              const float* __restrict__ gtb,
                                              int n, int m) {
    __shared__ float4 sg[MMAX];
    __shared__ float  sa[MMAX];
    __shared__ int    soff[GC * GC + 1];
    __shared__ unsigned char sidx[GIDX_CAP];
    __shared__ unsigned int s_nfg;
    int tid = threadIdx.x;
    if (tid == 0) s_nfg = 0u;
    for (int j = tid; j < m; j += blockDim.x) {
        float x1 = gtb[4 * j + 0], y1 = gtb[4 * j + 1];
        float x2 = gtb[4 * j + 2], y2 = gtb[4 * j + 3];
        sg[j] = make_float4(x1, y1, x2, y2);
        sa[j] = __fmul_rn(__fadd_rn(__fsub_rn(x2, x1), 1.0f),
                          __fadd_rn(__fsub_rn(y2, y1), 1.0f));
    }
    int total = g_goff[GC * GC];
    for (int c = tid; c < GC * GC + 1; c += blockDim.x) soff[c] = g_goff[c];
    for (int t = tid; t < total; t += blockDim.x) sidx[t] = g_gidx[t];
    __syncthreads();

    int base = blockIdx.x * blockDim.x * RPT + tid;
#pragma unroll
    for (int q = 0; q < RPT; q++) {
        int i = base + q * 256;
        if (i >= n) break;
        // --- exact JAX uniform (threefry_partitionable=True default):
        //     per-element u64 iota counter (0, i); 32-bit draw = o0 ^ o1
        uint32_t o0, o1;
        threefry_0_42(0u, (uint32_t)i, o0, o1);
        uint32_t raw = o0 ^ o1;
        float r = __uint_as_float((raw >> 9) | 0x3F800000u) - 1.0f;
        g_rbits[i] = __float_as_uint(r);

        // --- pruned IoU argmax (fp32-division ordering == reference)
        float4 a = reinterpret_cast<const float4*>(rois)[i];
        float areaA = __fmul_rn(__fadd_rn(__fsub_rn(a.z, a.x), 1.0f),
                                __fadd_rn(__fsub_rn(a.w, a.y), 1.0f));
        float bestIou = 0.0f;
        int arg = 0;
        int cx0 = cell_of(a.x - 2.0f), cx1 = cell_of(a.z + 2.0f);
        int cy0 = cell_of(a.y - 2.0f), cy1 = cell_of(a.w + 2.0f);
        for (int cy = cy0; cy <= cy1; cy++) {
            for (int cx = cx0; cx <= cx1; cx++) {
                int cell = cy * GC + cx;
                int b0 = soff[cell], b1 = soff[cell + 1];
                for (int t = b0; t < b1; t++) {
                    int j = sidx[t];
                    float4 g = sg[j];
                    float w = __fadd_rn(__fsub_rn(fminf(a.z, g.z),
                                                  fmaxf(a.x, g.x)), 1.0f);
                    float h = __fadd_rn(__fsub_rn(fminf(a.w, g.w),
                                                  fmaxf(a.y, g.y)), 1.0f);
                    if (w > 0.0f && h > 0.0f) {
                        float inter = __fmul_rn(w, h);
                        float u = __fsub_rn(__fadd_rn(areaA, sa[j]), inter);
                        float iou = __fdiv_rn(inter, u);
                        if (iou > bestIou || (iou == bestIou && j < arg)) {
                            bestIou = iou; arg = j;
                        }
                    }
                }
            }
        }
        g_argmax[i] = arg;

        int flag = 0;
        if (bestIou > 0.5f) flag = 1;
        else if (bestIou < 0.5f) flag = 2;
        g_flag[i] = (unsigned char)flag;
        if (flag) {
            uint32_t b = (uint32_t)(r * (float)NBUCK);  // monotone bucket map
            atomicAdd(&g_hist[(flag - 1) * NBUCK + b], 1u);
            if (flag == 1) atomicAdd(&s_nfg, 1u);
        }
    }
    __syncthreads();
    if (tid == 0 && s_nfg) atomicAdd(&g_nfg, s_nfg);
}

// ---------------- K2: suffix-scan histograms (block per class) ------------
__global__ void __launch_bounds__(1024) k_cutoff() {
    __shared__ unsigned int csum[1024];
    __shared__ unsigned int wsum[32];
    int c = blockIdx.x;
    unsigned int k = (c == 0) ? K_FG : K_BG;
    int tid = threadIdx.x;
    unsigned int s = 0;
    int base = c * NBUCK + tid * 4;
#pragma unroll
    for (int q = 0; q < 4; q++) s += g_hist[base + q];
    csum[tid] = s;
    __syncthreads();
    if (tid < 32) {
        unsigned int ws = 0;
#pragma unroll
        for (int q = 0; q < 32; q++) ws += csum[tid * 32 + q];
        wsum[tid] = ws;
    }
    __syncthreads();
    if (tid == 0) {
        unsigned int cum = 0;
        int wc = 31;
        for (; wc >= 0; wc--) { cum += wsum[wc]; if (cum >= k) break; }
        int cut = 0;
        if (wc >= 0) {
            unsigned int cum2 = cum - wsum[wc];
            int tc = wc * 32 + 31;
            for (; tc >= wc * 32; tc--) { cum2 += csum[tc]; if (cum2 >= k) break; }
            cum2 -= csum[tc];
            cut = tc * 4;
            for (int b = tc * 4 + 3; b >= tc * 4; b--) {
                cum2 += g_hist[c * NBUCK + b];
                if (cum2 >= k) { cut = b; break; }
            }
        }
        g_cut[c] = cut;
    }
}

// ---------------- K3: compact candidates above the cutoff -----------------
__global__ void k_compact(int n) {
    int i = blockIdx.x * blockDim.x + threadIdx.x;
    if (i >= n) return;
    int f = g_flag[i];
    if (!f) return;
    int c = f - 1;
    uint32_t rb = g_rbits[i];
    float r = __uint_as_float(rb);
    int b = (int)(r * (float)NBUCK);
    if (b >= g_cut[c]) {
        unsigned int p = atomicAdd(&g_candcnt[c], 1u);
        if (p < CAP) {
            // ascending sort key: smaller == larger r; tie -> lower index first
            g_cand[c * CAP + p] =
                ((unsigned long long)(~rb) << 32) | (unsigned int)i;
        }
    }
}

// ---------------- K4: bitonic sort (block 0 = fg, block 1 = bg) -----------
__global__ void __launch_bounds__(1024) k_sort() {
    __shared__ unsigned long long s[CAP];
    int c = blockIdx.x;
    unsigned int cnt = g_candcnt[c];
    if (cnt > CAP) cnt = CAP;
    int S = (cnt <= 1024) ? 1024 : CAP;   // dynamic pow2 sort size
    for (int t = threadIdx.x; t < S; t += 1024)
        s[t] = (t < (int)cnt) ? g_cand[c * CAP + t] : ~0ULL;
    __syncthreads();
    for (int k = 2; k <= S; k <<= 1) {
        for (int j = k >> 1; j > 0; j >>= 1) {
            for (int t = threadIdx.x; t < S; t += 1024) {
                int ixj = t ^ j;
                if (ixj > t) {
                    bool up = ((t & k) == 0);
                    unsigned long long a = s[t], b = s[ixj];
                    if ((a > b) == up) { s[t] = b; s[ixj] = a; }
                }
            }
            __syncthreads();
        }
    }
    int k_out = (c == 0) ? K_FG : K_BG;
    int off   = (c == 0) ? 0    : K_FG;
    for (int t = threadIdx.x; t < k_out; t += 1024)
        g_top[off + t] = (int)(unsigned int)(s[t] & 0xFFFFFFFFu);
}

// ---------------- K5: build all five outputs (float32, tuple order) -------
__global__ void __launch_bounds__(TOTAL) k_output(const float* __restrict__ rois,
                                                  const float* __restrict__ gtb,
                                                  const int* __restrict__ glab,
                                                  float* __restrict__ out, int n) {
    int s = threadIdx.x;
    if (s >= TOTAL) return;
    int nfg = min((int)g_nfg, K_FG);
    bool isfg = s < nfg;
    int keep;
    if (isfg) keep = g_top[s];
    else {
        int bs = s - nfg;
        bs = bs < 0 ? 0 : (bs > K_BG - 1 ? K_BG - 1 : bs);
        keep = g_top[K_FG + bs];
    }
    if (keep < 0 || keep >= n) keep = 0;   // safety (unreachable for this input)

    float rx1 = rois[4 * keep + 0], ry1 = rois[4 * keep + 1];
    float rx2 = rois[4 * keep + 2], ry2 = rois[4 * keep + 3];
    out[4 * s + 0] = rx1; out[4 * s + 1] = ry1;
    out[4 * s + 2] = rx2; out[4 * s + 3] = ry2;

    int ga  = g_argmax[keep];
    int lab = glab[ga];
    out[TOTAL * 4 + s] = isfg ? (float)lab : 0.0f;

    float e0 = 0.f, e1 = 0.f, e2 = 0.f, e3 = 0.f;
    if (isfg) {
        float gx1 = gtb[4 * ga + 0], gy1 = gtb[4 * ga + 1];
        float gx2 = gtb[4 * ga + 2], gy2 = gtb[4 * ga + 3];
        float rw = fmaxf(rx2 - rx1 + 1.0f, 1e-6f);
        float rh = fmaxf(ry2 - ry1 + 1.0f, 1e-6f);
        float rcx = rx1 + 0.5f * rw, rcy = ry1 + 0.5f * rh;
        float gw = fmaxf(gx2 - gx1 + 1.0f, 1e-6f);
        float gh = fmaxf(gy2 - gy1 + 1.0f, 1e-6f);
        float gcx = gx1 + 0.5f * gw, gcy = gy1 + 0.5f * gh;
        e0 = (gcx - rcx) / rw;
        e1 = (gcy - rcy) / rh;
        e2 = logf(gw / rw);
        e3 = logf(gh / rh);
    }

    const int TGT = TOTAL * 4 + TOTAL;           // 2560
    const int INW = TGT + TOTAL * NCLS * 4;      // 45568
    const int OUW = INW + TOTAL * NCLS * 4;      // 88576
    int L = isfg ? lab : -1;
#pragma unroll
    for (int c = 0; c < NCLS; c++) {
        bool hit = (c == L);
        int o = s * (NCLS * 4) + 4 * c;
        out[TGT + o + 0] = hit ? e0 : 0.f;
        out[TGT + o + 1] = hit ? e1 : 0.f;
        out[TGT + o + 2] = hit ? e2 : 0.f;
        out[TGT + o + 3] = hit ? e3 : 0.f;
        float w = hit ? 1.f : 0.f;
        out[INW + o + 0] = w; out[INW + o + 1] = w;
        out[INW + o + 2] = w; out[INW + o + 3] = w;
        out[OUW + o + 0] = 1.f; out[OUW + o + 1] = 1.f;
        out[OUW + o + 2] = 1.f; out[OUW + o + 3] = 1.f;
    }
}

// ---------------- launcher -------------------------------------------------
extern "C" void kernel_launch(void* const* d_in, const int* in_sizes, int n_in,
                              void* d_out, int out_size) {
    // Identify inputs by size (rois: 4N, gt_bboxes: 4M, gt_labels: M)
    int i_rois = 0;
    for (int i = 0; i < n_in; i++)
        if (in_sizes[i] > in_sizes[i_rois]) i_rois = i;
    int i_gtb = -1, i_lab = -1;
    {
        int a = -1, b = -1;
        for (int i = 0; i < n_in; i++) if (i != i_rois) { if (a < 0) a = i; else b = i; }
        if (in_sizes[a] < in_sizes[b]) { i_lab = a; i_gtb = b; }
        else                           { i_lab = b; i_gtb = a; }
    }

    const float* rois = (const float*)d_in[i_rois];
    const float* gtb  = (const float*)d_in[i_gtb];
    const int*   glab = (const int*)d_in[i_lab];
    float* out = (float*)d_out;

    int n = in_sizes[i_rois] / 4;
    if (n > NMAX) n = NMAX;
    int m = in_sizes[i_gtb] / 4;
    if (m > MMAX) m = MMAX;

    k_grid<<<1, 256>>>(gtb, m);
    k_main<<<(n + 256 * RPT - 1) / (256 * RPT), 256>>>(rois, gtb, n, m);
    k_cutoff<<<2, 1024>>>();
    k_compact<<<(n + 255) / 256, 256>>>(n);
    k_sort<<<2, 1024>>>();
    k_output<<<1, TOTAL>>>(rois, gtb, glab, out, n);
}

// round 5
// speedup vs baseline: 7.4646x; 2.4560x over previous
#include <cuda_runtime.h>
#include <stdint.h>

#define NBUCK 4096
#define CAP   2048
#define K_FG  128
#define K_BG  512
#define TOTAL 512
#define NCLS  21
#define NMAX  200000
#define MMAX  256
#define RPT   2              // rois per thread in k_main

#define GC       20          // 20x20 cells, 64px, origin -128 -> covers [-128,1152)
#define GORG     128.0f
#define GINV     (1.0f/64.0f)
#define GIDX_CAP 4608

// ---------------- global scratch (no allocations allowed) ----------------
__device__ unsigned int       g_hist[2 * NBUCK];
__device__ unsigned int       g_rbits[NMAX];
__device__ unsigned char      g_flag[NMAX];
__device__ unsigned int       g_nfg;
__device__ int                g_cut[2];
__device__ unsigned int       g_candcnt[2];
__device__ unsigned long long g_cand[2 * CAP];
__device__ int                g_top[K_FG + K_BG]; // fg[128] then bg[512]
__device__ int                g_goff[GC * GC + 1];
__device__ unsigned char      g_gidx[GIDX_CAP];

// ---------------- Threefry-2x32, key = (0, 42) -----------------------------
__device__ __forceinline__ uint32_t rotl32(uint32_t x, int d) {
    return (x << d) | (x >> (32 - d));
}
__device__ __forceinline__ void threefry_0_42(uint32_t x0, uint32_t x1,
                                              uint32_t& o0, uint32_t& o1) {
    const uint32_t ks0 = 0u, ks1 = 42u, ks2 = 0x1BD11BDAu ^ 0u ^ 42u;
    x0 += ks0; x1 += ks1;
#define TF_R(r) { x0 += x1; x1 = rotl32(x1, r); x1 ^= x0; }
    TF_R(13) TF_R(15) TF_R(26) TF_R(6)  x0 += ks1; x1 += ks2 + 1u;
    TF_R(17) TF_R(29) TF_R(16) TF_R(24) x0 += ks2; x1 += ks0 + 2u;
    TF_R(13) TF_R(15) TF_R(26) TF_R(6)  x0 += ks0; x1 += ks1 + 3u;
    TF_R(17) TF_R(29) TF_R(16) TF_R(24) x0 += ks1; x1 += ks2 + 4u;
    TF_R(13) TF_R(15) TF_R(26) TF_R(6)  x0 += ks2; x1 += ks0 + 5u;
#undef TF_R
    o0 = x0; o1 = x1;
}
__device__ __forceinline__ int cell_of(float x) {
    int c = (int)floorf((x + GORG) * GINV);
    return min(max(c, 0), GC - 1);
}

// ---------------- L1: zero scratch ----------------------------------------
__global__ void k_zero() {
    int i = blockIdx.x * blockDim.x + threadIdx.x;
    if (i < 2 * NBUCK) g_hist[i] = 0u;
    if (i == 0) { g_nfg = 0u; g_candcnt[0] = 0u; g_candcnt[1] = 0u; }
}

// ---------------- L2: build gt spatial grid (CSR, one block) ---------------
__global__ void __launch_bounds__(256) k_grid(const float* __restrict__ gtb, int m) {
    __shared__ int cnt[GC * GC];
    __shared__ int cur[GC * GC];
    int tid = threadIdx.x;
    for (int c = tid; c < GC * GC; c += blockDim.x) cnt[c] = 0;
    __syncthreads();
    for (int j = tid; j < m; j += blockDim.x) {
        int cx0 = cell_of(gtb[4 * j + 0]), cy0 = cell_of(gtb[4 * j + 1]);
        int cx1 = cell_of(gtb[4 * j + 2]), cy1 = cell_of(gtb[4 * j + 3]);
        for (int cy = cy0; cy <= cy1; cy++)
            for (int cx = cx0; cx <= cx1; cx++)
                atomicAdd(&cnt[cy * GC + cx], 1);
    }
    __syncthreads();
    if (tid == 0) {
        int acc = 0;
        for (int c = 0; c < GC * GC; c++) { cur[c] = acc; g_goff[c] = acc; acc += cnt[c]; }
        g_goff[GC * GC] = acc;
    }
    __syncthreads();
    for (int j = tid; j < m; j += blockDim.x) {
        int cx0 = cell_of(gtb[4 * j + 0]), cy0 = cell_of(gtb[4 * j + 1]);
        int cx1 = cell_of(gtb[4 * j + 2]), cy1 = cell_of(gtb[4 * j + 3]);
        for (int cy = cy0; cy <= cy1; cy++)
            for (int cx = cx0; cx <= cx1; cx++) {
                int p = atomicAdd(&cur[cy * GC + cx], 1);
                g_gidx[p] = (unsigned char)j;
            }
    }
}

// ---------------- L3: PRNG (exact JAX partitionable threefry) --------------
__global__ void k_rand(int n) {
    int i = blockIdx.x * blockDim.x + threadIdx.x;
    if (i >= n) return;
    uint32_t o0, o1;
    threefry_0_42(0u, (uint32_t)i, o0, o1);   // u64 iota counter (0, i)
    uint32_t raw = o0 ^ o1;                   // 32-bit draw combine
    float r = __uint_as_float((raw >> 9) | 0x3F800000u) - 1.0f;
    g_rbits[i] = __float_as_uint(r);
}

// ---------------- L4: classification (division-free) + histogram ----------
__global__ void __launch_bounds__(256) k_main(const float* __restrict__ rois,
                                              const float* __restrict__ gtb,
                                              int n, int m) {
    __shared__ float4 sg[MMAX];
    __shared__ float  sa[MMAX];
    __shared__ int    soff[GC * GC + 1];
    __shared__ unsigned char sidx[GIDX_CAP];
    __shared__ unsigned int s_nfg;
    int tid = threadIdx.x;
    if (tid == 0) s_nfg = 0u;
    for (int j = tid; j < m; j += blockDim.x) {
        float x1 = gtb[4 * j + 0], y1 = gtb[4 * j + 1];
        float x2 = gtb[4 * j + 2], y2 = gtb[4 * j + 3];
        sg[j] = make_float4(x1, y1, x2, y2);
        sa[j] = __fmul_rn(__fadd_rn(__fsub_rn(x2, x1), 1.0f),
                          __fadd_rn(__fsub_rn(y2, y1), 1.0f));
    }
    int total = g_goff[GC * GC];
    for (int c = tid; c < GC * GC + 1; c += blockDim.x) soff[c] = g_goff[c];
    for (int t = tid; t < total; t += blockDim.x) sidx[t] = g_gidx[t];
    __syncthreads();

    int base = blockIdx.x * blockDim.x * RPT + tid;
#pragma unroll
    for (int q = 0; q < RPT; q++) {
        int i = base + q * 256;
        if (i >= n) break;

        float4 a = reinterpret_cast<const float4*>(rois)[i];
        float areaA = __fmul_rn(__fadd_rn(__fsub_rn(a.z, a.x), 1.0f),
                                __fadd_rn(__fsub_rn(a.w, a.y), 1.0f));
        bool any_gt = false, any_ge = false;
        int cx0 = cell_of(a.x - 2.0f), cx1 = cell_of(a.z + 2.0f);
        int cy0 = cell_of(a.y - 2.0f), cy1 = cell_of(a.w + 2.0f);
        for (int cy = cy0; cy <= cy1; cy++) {
            for (int cx = cx0; cx <= cx1; cx++) {
                int cell = cy * GC + cx;
                int b0 = soff[cell], b1 = soff[cell + 1];
                for (int t = b0; t < b1; t++) {
                    int j = sidx[t];
                    float4 g = sg[j];
                    float w = __fadd_rn(__fsub_rn(fminf(a.z, g.z),
                                                  fmaxf(a.x, g.x)), 1.0f);
                    float h = __fadd_rn(__fsub_rn(fminf(a.w, g.w),
                                                  fmaxf(a.y, g.y)), 1.0f);
                    bool ovl = (w > 0.0f) && (h > 0.0f);
                    float inter = __fmul_rn(w, h);
                    float u = __fsub_rn(__fadd_rn(areaA, sa[j]), inter);
                    // sign of (inter - 0.5*u) == sign of (iou - 0.5) exactly
                    float d = __fmaf_rn(-0.5f, u, inter);
                    bool gtp = ovl && (d > 0.0f);
                    bool gep = gtp;
                    if (ovl && fabsf(d) <= 1e-6f * u) {  // ~never taken
                        float rh = __fdiv_rn(inter, u);  // exact ref verdict
                        gtp = rh > 0.5f; gep = rh >= 0.5f;
                    }
                    any_gt |= gtp; any_ge |= gep;
                }
            }
        }
        int flag = any_gt ? 1 : (any_ge ? 0 : 2);
        g_flag[i] = (unsigned char)flag;
        if (flag) {
            float r = __uint_as_float(g_rbits[i]);
            uint32_t b = (uint32_t)(r * (float)NBUCK);  // monotone bucket map
            atomicAdd(&g_hist[(flag - 1) * NBUCK + b], 1u);
            if (flag == 1) atomicAdd(&s_nfg, 1u);
        }
    }
    __syncthreads();
    if (tid == 0 && s_nfg) atomicAdd(&g_nfg, s_nfg);
}

// ---------------- L5: suffix-scan histograms (block per class) -------------
__global__ void __launch_bounds__(1024) k_cutoff() {
    __shared__ unsigned int csum[1024];
    __shared__ unsigned int wsum[32];
    int c = blockIdx.x;
    unsigned int k = (c == 0) ? K_FG : K_BG;
    int tid = threadIdx.x;
    unsigned int s = 0;
    int base = c * NBUCK + tid * 4;
#pragma unroll
    for (int q = 0; q < 4; q++) s += g_hist[base + q];
    csum[tid] = s;
    __syncthreads();
    if (tid < 32) {
        unsigned int ws = 0;
#pragma unroll
        for (int q = 0; q < 32; q++) ws += csum[tid * 32 + q];
        wsum[tid] = ws;
    }
    __syncthreads();
    if (tid == 0) {
        unsigned int cum = 0;
        int wc = 31;
        for (; wc >= 0; wc--) { cum += wsum[wc]; if (cum >= k) break; }
        int cut = 0;
        if (wc >= 0) {
            unsigned int cum2 = cum - wsum[wc];
            int tc = wc * 32 + 31;
            for (; tc >= wc * 32; tc--) { cum2 += csum[tc]; if (cum2 >= k) break; }
            cum2 -= csum[tc];
            cut = tc * 4;
            for (int b = tc * 4 + 3; b >= tc * 4; b--) {
                cum2 += g_hist[c * NBUCK + b];
                if (cum2 >= k) { cut = b; break; }
            }
        }
        g_cut[c] = cut;
    }
}

// ---------------- L6: compact candidates above the cutoff ------------------
__global__ void k_compact(int n) {
    int i = blockIdx.x * blockDim.x + threadIdx.x;
    if (i >= n) return;
    int f = g_flag[i];
    if (!f) return;
    int c = f - 1;
    uint32_t rb = g_rbits[i];
    float r = __uint_as_float(rb);
    int b = (int)(r * (float)NBUCK);
    if (b >= g_cut[c]) {
        unsigned int p = atomicAdd(&g_candcnt[c], 1u);
        if (p < CAP)
            g_cand[c * CAP + p] =
                ((unsigned long long)(~rb) << 32) | (unsigned int)i;
    }
}

// ---------------- L7: bitonic sort (block 0 = fg, block 1 = bg) ------------
__global__ void __launch_bounds__(1024) k_sort() {
    __shared__ unsigned long long s[CAP];
    int c = blockIdx.x;
    unsigned int cnt = g_candcnt[c];
    if (cnt > CAP) cnt = CAP;
    int S = (cnt <= 1024) ? 1024 : CAP;
    for (int t = threadIdx.x; t < S; t += 1024)
        s[t] = (t < (int)cnt) ? g_cand[c * CAP + t] : ~0ULL;
    __syncthreads();
    for (int k = 2; k <= S; k <<= 1) {
        for (int j = k >> 1; j > 0; j >>= 1) {
            for (int t = threadIdx.x; t < S; t += 1024) {
                int ixj = t ^ j;
                if (ixj > t) {
                    bool up = ((t & k) == 0);
                    unsigned long long a = s[t], b = s[ixj];
                    if ((a > b) == up) { s[t] = b; s[ixj] = a; }
                }
            }
            __syncthreads();
        }
    }
    int k_out = (c == 0) ? K_FG : K_BG;
    int off   = (c == 0) ? 0    : K_FG;
    for (int t = threadIdx.x; t < k_out; t += 1024)
        g_top[off + t] = (int)(unsigned int)(s[t] & 0xFFFFFFFFu);
}

// ---------------- L8: per-keep argmax + all five outputs -------------------
__global__ void __launch_bounds__(64) k_outarg(const float* __restrict__ rois,
                                               const float* __restrict__ gtb,
                                               const int* __restrict__ glab,
                                               float* __restrict__ out,
                                               int n, int m) {
    __shared__ unsigned long long sred[2];
    int s = blockIdx.x;
    int tid = threadIdx.x;

    int nfg = min((int)g_nfg, K_FG);
    bool isfg = s < nfg;
    int keep;
    if (isfg) keep = g_top[s];
    else {
        int bs = s - nfg;
        bs = bs < 0 ? 0 : (bs > K_BG - 1 ? K_BG - 1 : bs);
        keep = g_top[K_FG + bs];
    }
    if (keep < 0 || keep >= n) keep = 0;

    float4 a = reinterpret_cast<const float4*>(rois)[keep];
    float areaA = __fmul_rn(__fadd_rn(__fsub_rn(a.z, a.x), 1.0f),
                            __fadd_rn(__fsub_rn(a.w, a.y), 1.0f));

    // exact reference argmax: fp32 iou, first max wins
    unsigned long long best = 0ULL;
    for (int j = tid; j < m; j += 64) {
        float gx1 = gtb[4 * j + 0], gy1 = gtb[4 * j + 1];
        float gx2 = gtb[4 * j + 2], gy2 = gtb[4 * j + 3];
        float areaG = __fmul_rn(__fadd_rn(__fsub_rn(gx2, gx1), 1.0f),
                                __fadd_rn(__fsub_rn(gy2, gy1), 1.0f));
        float w = __fadd_rn(__fsub_rn(fminf(a.z, gx2), fmaxf(a.x, gx1)), 1.0f);
        float h = __fadd_rn(__fsub_rn(fminf(a.w, gy2), fmaxf(a.y, gy1)), 1.0f);
        w = fmaxf(w, 0.0f); h = fmaxf(h, 0.0f);
        float inter = __fmul_rn(w, h);
        float u = __fsub_rn(__fadd_rn(areaA, areaG), inter);
        float iou = __fdiv_rn(inter, u);
        if (!(inter > 0.0f)) iou = 0.0f;
        unsigned long long key =
            ((unsigned long long)__float_as_uint(iou) << 32) |
            (unsigned long long)(0xFFFFFFFFu - (unsigned)j);
        if (key > best) best = key;
    }
#pragma unroll
    for (int o = 16; o > 0; o >>= 1) {
        unsigned long long v = __shfl_down_sync(0xFFFFFFFFu, best, o);
        if (v > best) best = v;
    }
    if ((tid & 31) == 0) sred[tid >> 5] = best;
    __syncthreads();
    unsigned long long tot = sred[0] > sred[1] ? sred[0] : sred[1];
    int ga = (int)(0xFFFFFFFFu - (unsigned)(tot & 0xFFFFFFFFu));

    int lab = glab[ga];
    float e0 = 0.f, e1 = 0.f, e2 = 0.f, e3 = 0.f;
    if (isfg) {
        float gx1 = gtb[4 * ga + 0], gy1 = gtb[4 * ga + 1];
        float gx2 = gtb[4 * ga + 2], gy2 = gtb[4 * ga + 3];
        float rw = fmaxf(a.z - a.x + 1.0f, 1e-6f);
        float rh = fmaxf(a.w - a.y + 1.0f, 1e-6f);
        float rcx = a.x + 0.5f * rw, rcy = a.y + 0.5f * rh;
        float gw = fmaxf(gx2 - gx1 + 1.0f, 1e-6f);
        float gh = fmaxf(gy2 - gy1 + 1.0f, 1e-6f);
        float gcx = gx1 + 0.5f * gw, gcy = gy1 + 0.5f * gh;
        e0 = (gcx - rcx) / rw;
        e1 = (gcy - rcy) / rh;
        e2 = logf(gw / rw);
        e3 = logf(gh / rh);
    }

    const int TGT = TOTAL * 4 + TOTAL;           // 2560
    const int INW = TGT + TOTAL * NCLS * 4;      // 45568
    const int OUW = INW + TOTAL * NCLS * 4;      // 88576
    if (tid == 0) {
        out[4 * s + 0] = a.x; out[4 * s + 1] = a.y;
        out[4 * s + 2] = a.z; out[4 * s + 3] = a.w;
        out[TOTAL * 4 + s] = isfg ? (float)lab : 0.0f;
    }
    int L = isfg ? lab : -1;
    for (int idx = tid; idx < NCLS * 4; idx += 64) {
        int c = idx >> 2, k = idx & 3;
        bool hit = (c == L);
        float ev = (k == 0) ? e0 : (k == 1) ? e1 : (k == 2) ? e2 : e3;
        int o = s * (NCLS * 4) + idx;
        out[TGT + o] = hit ? ev : 0.f;
        out[INW + o] = hit ? 1.f : 0.f;
        out[OUW + o] = 1.f;
    }
}

// ---------------- launcher -------------------------------------------------
extern "C" void kernel_launch(void* const* d_in, const int* in_sizes, int n_in,
                              void* d_out, int out_size) {
    int i_rois = 0;
    for (int i = 0; i < n_in; i++)
        if (in_sizes[i] > in_sizes[i_rois]) i_rois = i;
    int i_gtb = -1, i_lab = -1;
    {
        int a = -1, b = -1;
        for (int i = 0; i < n_in; i++) if (i != i_rois) { if (a < 0) a = i; else b = i; }
        if (in_sizes[a] < in_sizes[b]) { i_lab = a; i_gtb = b; }
        else                           { i_lab = b; i_gtb = a; }
    }

    const float* rois = (const float*)d_in[i_rois];
    const float* gtb  = (const float*)d_in[i_gtb];
    const int*   glab = (const int*)d_in[i_lab];
    float* out = (float*)d_out;

    int n = in_sizes[i_rois] / 4;
    if (n > NMAX) n = NMAX;
    int m = in_sizes[i_gtb] / 4;
    if (m > MMAX) m = MMAX;

    k_zero<<<(2 * NBUCK + 255) / 256, 256>>>();
    k_grid<<<1, 256>>>(gtb, m);
    k_rand<<<(n + 255) / 256, 256>>>(n);
    k_main<<<(n + 256 * RPT - 1) / (256 * RPT), 256>>>(rois, gtb, n, m);  // launch #4 -> ncu
    k_cutoff<<<2, 1024>>>();
    k_compact<<<(n + 255) / 256, 256>>>(n);
    k_sort<<<2, 1024>>>();
    k_outarg<<<TOTAL, 64>>>(rois, gtb, glab, out, n, m);
}

// round 6
// speedup vs baseline: 7.9239x; 1.0615x over previous
#include <cuda_runtime.h>
#include <stdint.h>

#define NBUCK 4096
#define CAP   2048
#define K_FG  128
#define K_BG  512
#define TOTAL 512
#define NCLS  21
#define NMAX  200000
#define MMAX  256

#define GC       20          // 20x20 cells, 64px, origin -128 -> covers [-128,1152)
#define GORG     128.0f
#define GINV     (1.0f/64.0f)
#define GIDX_CAP 4608

// ---------------- global scratch (no allocations allowed) ----------------
__device__ unsigned int       g_hist[2 * NBUCK];
__device__ unsigned int       g_rbits[NMAX];
__device__ unsigned char      g_flag[NMAX];
__device__ unsigned int       g_nfg;
__device__ int                g_cut[2];
__device__ unsigned int       g_candcnt[2];
__device__ unsigned long long g_cand[2 * CAP];
__device__ int                g_top[K_FG + K_BG]; // fg[128] then bg[512]
__device__ int                g_goff[GC * GC + 1];
__device__ unsigned char      g_gidx[GIDX_CAP];

// ---------------- Threefry-2x32, key = (0, 42) -----------------------------
__device__ __forceinline__ uint32_t rotl32(uint32_t x, int d) {
    return (x << d) | (x >> (32 - d));
}
__device__ __forceinline__ void threefry_0_42(uint32_t x0, uint32_t x1,
                                              uint32_t& o0, uint32_t& o1) {
    const uint32_t ks0 = 0u, ks1 = 42u, ks2 = 0x1BD11BDAu ^ 0u ^ 42u;
    x0 += ks0; x1 += ks1;
#define TF_R(r) { x0 += x1; x1 = rotl32(x1, r); x1 ^= x0; }
    TF_R(13) TF_R(15) TF_R(26) TF_R(6)  x0 += ks1; x1 += ks2 + 1u;
    TF_R(17) TF_R(29) TF_R(16) TF_R(24) x0 += ks2; x1 += ks0 + 2u;
    TF_R(13) TF_R(15) TF_R(26) TF_R(6)  x0 += ks0; x1 += ks1 + 3u;
    TF_R(17) TF_R(29) TF_R(16) TF_R(24) x0 += ks1; x1 += ks2 + 4u;
    TF_R(13) TF_R(15) TF_R(26) TF_R(6)  x0 += ks2; x1 += ks0 + 5u;
#undef TF_R
    o0 = x0; o1 = x1;
}
__device__ __forceinline__ int cell_of(float x) {
    int c = (int)floorf((x + GORG) * GINV);
    return min(max(c, 0), GC - 1);
}

// ---------------- L1: fused prep: PRNG + hist zero + gt grid build ---------
__global__ void __launch_bounds__(256) k_prep(const float* __restrict__ gtb,
                                              int n, int m) {
    int tid = threadIdx.x;
    if (blockIdx.x == gridDim.x - 1) {
        // --- last block: build gt spatial grid (CSR) + zero scalars
        __shared__ int cnt[GC * GC];
        __shared__ int cur[GC * GC];
        if (tid == 0) { g_nfg = 0u; g_candcnt[0] = 0u; g_candcnt[1] = 0u; }
        for (int c = tid; c < GC * GC; c += 256) cnt[c] = 0;
        __syncthreads();
        for (int j = tid; j < m; j += 256) {
            int cx0 = cell_of(gtb[4 * j + 0]), cy0 = cell_of(gtb[4 * j + 1]);
            int cx1 = cell_of(gtb[4 * j + 2]), cy1 = cell_of(gtb[4 * j + 3]);
            for (int cy = cy0; cy <= cy1; cy++)
                for (int cx = cx0; cx <= cx1; cx++)
                    atomicAdd(&cnt[cy * GC + cx], 1);
        }
        __syncthreads();
        if (tid == 0) {
            int acc = 0;
            for (int c = 0; c < GC * GC; c++) {
                cur[c] = acc; g_goff[c] = acc; acc += cnt[c];
            }
            g_goff[GC * GC] = acc;
        }
        __syncthreads();
        for (int j = tid; j < m; j += 256) {
            int cx0 = cell_of(gtb[4 * j + 0]), cy0 = cell_of(gtb[4 * j + 1]);
            int cx1 = cell_of(gtb[4 * j + 2]), cy1 = cell_of(gtb[4 * j + 3]);
            for (int cy = cy0; cy <= cy1; cy++)
                for (int cx = cx0; cx <= cx1; cx++) {
                    int p = atomicAdd(&cur[cy * GC + cx], 1);
                    g_gidx[p] = (unsigned char)j;
                }
        }
        return;
    }
    int i = blockIdx.x * 256 + tid;
    if (i < 2 * NBUCK) g_hist[i] = 0u;
    if (i < n) {
        uint32_t o0, o1;
        threefry_0_42(0u, (uint32_t)i, o0, o1);   // u64 iota counter (0, i)
        uint32_t raw = o0 ^ o1;                   // 32-bit draw combine
        float r = __uint_as_float((raw >> 9) | 0x3F800000u) - 1.0f;
        g_rbits[i] = __float_as_uint(r);
    }
}

// ---------------- L2: classification (division-free) + histogram ----------
__global__ void __launch_bounds__(256) k_main(const float* __restrict__ rois,
                                              const float* __restrict__ gtb,
                                              int n, int m) {
    __shared__ float4 sg[MMAX];
    __shared__ float  sa[MMAX];
    __shared__ int    soff[GC * GC + 1];
    __shared__ unsigned char sidx[GIDX_CAP];
    __shared__ unsigned int s_nfg;
    int tid = threadIdx.x;
    if (tid == 0) s_nfg = 0u;
    for (int j = tid; j < m; j += blockDim.x) {
        float x1 = gtb[4 * j + 0], y1 = gtb[4 * j + 1];
        float x2 = gtb[4 * j + 2], y2 = gtb[4 * j + 3];
        sg[j] = make_float4(x1, y1, x2, y2);
        sa[j] = __fmul_rn(__fadd_rn(__fsub_rn(x2, x1), 1.0f),
                          __fadd_rn(__fsub_rn(y2, y1), 1.0f));
    }
    int total = g_goff[GC * GC];
    for (int c = tid; c < GC * GC + 1; c += blockDim.x) soff[c] = g_goff[c];
    for (int t = tid; t < total; t += blockDim.x) sidx[t] = g_gidx[t];
    __syncthreads();

    int i = blockIdx.x * blockDim.x + tid;
    if (i < n) {
        float4 a = reinterpret_cast<const float4*>(rois)[i];
        float areaA = __fmul_rn(__fadd_rn(__fsub_rn(a.z, a.x), 1.0f),
                                __fadd_rn(__fsub_rn(a.w, a.y), 1.0f));
        bool any_gt = false, any_ge = false;
        int cx0 = cell_of(a.x - 2.0f), cx1 = cell_of(a.z + 2.0f);
        int cy0 = cell_of(a.y - 2.0f), cy1 = cell_of(a.w + 2.0f);
        for (int cy = cy0; cy <= cy1; cy++) {
            for (int cx = cx0; cx <= cx1; cx++) {
                int cell = cy * GC + cx;
                int b0 = soff[cell], b1 = soff[cell + 1];
                for (int t = b0; t < b1; t++) {
                    int j = sidx[t];
                    float4 g = sg[j];
                    float w = __fadd_rn(__fsub_rn(fminf(a.z, g.z),
                                                  fmaxf(a.x, g.x)), 1.0f);
                    float h = __fadd_rn(__fsub_rn(fminf(a.w, g.w),
                                                  fmaxf(a.y, g.y)), 1.0f);
                    bool ovl = (w > 0.0f) && (h > 0.0f);
                    float inter = __fmul_rn(w, h);
                    float u = __fsub_rn(__fadd_rn(areaA, sa[j]), inter);
                    // sign of (inter - 0.5*u) == sign of (iou - 0.5) exactly
                    float d = __fmaf_rn(-0.5f, u, inter);
                    bool gtp = ovl && (d > 0.0f);
                    bool gep = gtp;
                    if (ovl && fabsf(d) <= 1e-6f * u) {  // ~never taken
                        float rh = __fdiv_rn(inter, u);  // exact ref verdict
                        gtp = rh > 0.5f; gep = rh >= 0.5f;
                    }
                    any_gt |= gtp; any_ge |= gep;
                }
            }
        }
        int flag = any_gt ? 1 : (any_ge ? 0 : 2);
        g_flag[i] = (unsigned char)flag;
        if (flag) {
            float r = __uint_as_float(g_rbits[i]);
            uint32_t b = (uint32_t)(r * (float)NBUCK);  // monotone bucket map
            atomicAdd(&g_hist[(flag - 1) * NBUCK + b], 1u);
            if (flag == 1) atomicAdd(&s_nfg, 1u);
        }
    }
    __syncthreads();
    if (tid == 0 && s_nfg) atomicAdd(&g_nfg, s_nfg);
}

// ---------------- L3: suffix-scan histograms (block per class) -------------
__global__ void __launch_bounds__(1024) k_cutoff() {
    __shared__ unsigned int csum[1024];
    __shared__ unsigned int wsum[32];
    int c = blockIdx.x;
    unsigned int k = (c == 0) ? K_FG : K_BG;
    int tid = threadIdx.x;
    unsigned int s = 0;
    int base = c * NBUCK + tid * 4;
#pragma unroll
    for (int q = 0; q < 4; q++) s += g_hist[base + q];
    csum[tid] = s;
    __syncthreads();
    if (tid < 32) {
        unsigned int ws = 0;
#pragma unroll
        for (int q = 0; q < 32; q++) ws += csum[tid * 32 + q];
        wsum[tid] = ws;
    }
    __syncthreads();
    if (tid == 0) {
        unsigned int cum = 0;
        int wc = 31;
        for (; wc >= 0; wc--) { cum += wsum[wc]; if (cum >= k) break; }
        int cut = 0;
        if (wc >= 0) {
            unsigned int cum2 = cum - wsum[wc];
            int tc = wc * 32 + 31;
            for (; tc >= wc * 32; tc--) { cum2 += csum[tc]; if (cum2 >= k) break; }
            cum2 -= csum[tc];
            cut = tc * 4;
            for (int b = tc * 4 + 3; b >= tc * 4; b--) {
                cum2 += g_hist[c * NBUCK + b];
                if (cum2 >= k) { cut = b; break; }
            }
        }
        g_cut[c] = cut;
    }
}

// ---------------- L4: compact candidates above the cutoff ------------------
__global__ void k_compact(int n) {
    int i = blockIdx.x * blockDim.x + threadIdx.x;
    if (i >= n) return;
    int f = g_flag[i];
    if (!f) return;
    int c = f - 1;
    uint32_t rb = g_rbits[i];
    float r = __uint_as_float(rb);
    int b = (int)(r * (float)NBUCK);
    if (b >= g_cut[c]) {
        unsigned int p = atomicAdd(&g_candcnt[c], 1u);
        if (p < CAP)
            g_cand[c * CAP + p] =
                ((unsigned long long)(~rb) << 32) | (unsigned int)i;
    }
}

// ---------------- L5: bitonic sort (block 0 = fg, block 1 = bg) ------------
__global__ void __launch_bounds__(1024) k_sort() {
    __shared__ unsigned long long s[CAP];
    int c = blockIdx.x;
    unsigned int cnt = g_candcnt[c];
    if (cnt > CAP) cnt = CAP;
    int k_out = (c == 0) ? K_FG : K_BG;
    int S = 256;
    while (S < (int)cnt || S < k_out) S <<= 1;   // pow2 size >= max(cnt,k)
    for (int t = threadIdx.x; t < S; t += 1024)
        s[t] = (t < (int)cnt) ? g_cand[c * CAP + t] : ~0ULL;
    __syncthreads();
    for (int k = 2; k <= S; k <<= 1) {
        for (int j = k >> 1; j > 0; j >>= 1) {
            for (int t = threadIdx.x; t < S; t += 1024) {
                int ixj = t ^ j;
                if (ixj > t) {
                    bool up = ((t & k) == 0);
                    unsigned long long a = s[t], b = s[ixj];
                    if ((a > b) == up) { s[t] = b; s[ixj] = a; }
                }
            }
            __syncthreads();
        }
    }
    int off = (c == 0) ? 0 : K_FG;
    for (int t = threadIdx.x; t < k_out; t += 1024)
        g_top[off + t] = (int)(unsigned int)(s[t] & 0xFFFFFFFFu);
}

// ---------------- L6: per-keep argmax + all five outputs -------------------
__global__ void __launch_bounds__(64) k_outarg(const float* __restrict__ rois,
                                               const float* __restrict__ gtb,
                                               const int* __restrict__ glab,
                                               float* __restrict__ out,
                                               int n, int m) {
    __shared__ unsigned long long sred[2];
    int s = blockIdx.x;
    int tid = threadIdx.x;

    int nfg = min((int)g_nfg, K_FG);
    bool isfg = s < nfg;
    int keep;
    if (isfg) keep = g_top[s];
    else {
        int bs = s - nfg;
        bs = bs < 0 ? 0 : (bs > K_BG - 1 ? K_BG - 1 : bs);
        keep = g_top[K_FG + bs];
    }
    if (keep < 0 || keep >= n) keep = 0;

    float4 a = reinterpret_cast<const float4*>(rois)[keep];
    float areaA = __fmul_rn(__fadd_rn(__fsub_rn(a.z, a.x), 1.0f),
                            __fadd_rn(__fsub_rn(a.w, a.y), 1.0f));

    // exact reference argmax: fp32 iou, first max wins
    unsigned long long best = 0ULL;
    for (int j = tid; j < m; j += 64) {
        float gx1 = gtb[4 * j + 0], gy1 = gtb[4 * j + 1];
        float gx2 = gtb[4 * j + 2], gy2 = gtb[4 * j + 3];
        float areaG = __fmul_rn(__fadd_rn(__fsub_rn(gx2, gx1), 1.0f),
                                __fadd_rn(__fsub_rn(gy2, gy1), 1.0f));
        float w = __fadd_rn(__fsub_rn(fminf(a.z, gx2), fmaxf(a.x, gx1)), 1.0f);
        float h = __fadd_rn(__fsub_rn(fminf(a.w, gy2), fmaxf(a.y, gy1)), 1.0f);
        w = fmaxf(w, 0.0f); h = fmaxf(h, 0.0f);
        float inter = __fmul_rn(w, h);
        float u = __fsub_rn(__fadd_rn(areaA, areaG), inter);
        float iou = __fdiv_rn(inter, u);
        if (!(inter > 0.0f)) iou = 0.0f;
        unsigned long long key =
            ((unsigned long long)__float_as_uint(iou) << 32) |
            (unsigned long long)(0xFFFFFFFFu - (unsigned)j);
        if (key > best) best = key;
    }
#pragma unroll
    for (int o = 16; o > 0; o >>= 1) {
        unsigned long long v = __shfl_down_sync(0xFFFFFFFFu, best, o);
        if (v > best) best = v;
    }
    if ((tid & 31) == 0) sred[tid >> 5] = best;
    __syncthreads();
    unsigned long long tot = sred[0] > sred[1] ? sred[0] : sred[1];
    int ga = (int)(0xFFFFFFFFu - (unsigned)(tot & 0xFFFFFFFFu));

    int lab = glab[ga];
    float e0 = 0.f, e1 = 0.f, e2 = 0.f, e3 = 0.f;
    if (isfg) {
        float gx1 = gtb[4 * ga + 0], gy1 = gtb[4 * ga + 1];
        float gx2 = gtb[4 * ga + 2], gy2 = gtb[4 * ga + 3];
        float rw = fmaxf(a.z - a.x + 1.0f, 1e-6f);
        float rh = fmaxf(a.w - a.y + 1.0f, 1e-6f);
        float rcx = a.x + 0.5f * rw, rcy = a.y + 0.5f * rh;
        float gw = fmaxf(gx2 - gx1 + 1.0f, 1e-6f);
        float gh = fmaxf(gy2 - gy1 + 1.0f, 1e-6f);
        float gcx = gx1 + 0.5f * gw, gcy = gy1 + 0.5f * gh;
        e0 = (gcx - rcx) / rw;
        e1 = (gcy - rcy) / rh;
        e2 = logf(gw / rw);
        e3 = logf(gh / rh);
    }

    const int TGT = TOTAL * 4 + TOTAL;           // 2560
    const int INW = TGT + TOTAL * NCLS * 4;      // 45568
    const int OUW = INW + TOTAL * NCLS * 4;      // 88576
    if (tid == 0) {
        out[4 * s + 0] = a.x; out[4 * s + 1] = a.y;
        out[4 * s + 2] = a.z; out[4 * s + 3] = a.w;
        out[TOTAL * 4 + s] = isfg ? (float)lab : 0.0f;
    }
    int L = isfg ? lab : -1;
    for (int idx = tid; idx < NCLS * 4; idx += 64) {
        int c = idx >> 2, k = idx & 3;
        bool hit = (c == L);
        float ev = (k == 0) ? e0 : (k == 1) ? e1 : (k == 2) ? e2 : e3;
        int o = s * (NCLS * 4) + idx;
        out[TGT + o] = hit ? ev : 0.f;
        out[INW + o] = hit ? 1.f : 0.f;
        out[OUW + o] = 1.f;
    }
}

// ---------------- launcher -------------------------------------------------
extern "C" void kernel_launch(void* const* d_in, const int* in_sizes, int n_in,
                              void* d_out, int out_size) {
    int i_rois = 0;
    for (int i = 0; i < n_in; i++)
        if (in_sizes[i] > in_sizes[i_rois]) i_rois = i;
    int i_gtb = -1, i_lab = -1;
    {
        int a = -1, b = -1;
        for (int i = 0; i < n_in; i++) if (i != i_rois) { if (a < 0) a = i; else b = i; }
        if (in_sizes[a] < in_sizes[b]) { i_lab = a; i_gtb = b; }
        else                           { i_lab = b; i_gtb = a; }
    }

    const float* rois = (const float*)d_in[i_rois];
    const float* gtb  = (const float*)d_in[i_gtb];
    const int*   glab = (const int*)d_in[i_lab];
    float* out = (float*)d_out;

    int n = in_sizes[i_rois] / 4;
    if (n > NMAX) n = NMAX;
    int m = in_sizes[i_gtb] / 4;
    if (m > MMAX) m = MMAX;

    int nb = (n + 255) / 256;                 // rand/zero blocks
    k_prep<<<nb + 1, 256>>>(gtb, n, m);       // +1 block builds the gt grid
    k_main<<<nb, 256>>>(rois, gtb, n, m);
    k_cutoff<<<2, 1024>>>();
    k_compact<<<nb, 256>>>(n);
    k_sort<<<2, 1024>>>();
    k_outarg<<<TOTAL, 64>>>(rois, gtb, glab, out, n, m);
}